// round 14
// baseline (speedup 1.0000x reference)
#include <cuda_runtime.h>
#include <math.h>

#define BATCH 256
#define NNODE 184
#define HID   128
#define TH    24
#define TF    24
#define M_ROWS (BATCH*NNODE)      /* 47104 = 368*128 */
#define GCOLS  (3*HID)            /* 384 */

// ---------------- persistent device scratch ----------------
// h stored FRAGMENT-DIRECT per row (128 words):
//   uint4 at word offset it*16 + q*4 = { bf16x2(hi_{k+1},hi_k), bf16x2(hi_{k+9},hi_{k+8}),
//                                        bf16x2(lo_{k+1},lo_k), bf16x2(lo_{k+9},lo_{k+8}) }
//   with k = it*16 + 2q. One LDG.128 -> MMA-ready hi & lo A fragments (zero PRMT).
__device__ unsigned g_hpA[(size_t)M_ROWS*HID];
__device__ unsigned g_hpB[(size_t)M_ROWS*HID];
__device__ float g_xn[M_ROWS];
__device__ float g_xnpart[8*M_ROWS];             // per-16hu-group fc partial sums
__device__ float g_x2[(size_t)M_ROWS*9];         // fore GRU input feats [f0..f7, g]
__device__ float g_comp1[NNODE*NNODE];
__device__ float g_comp2[NNODE*NNODE];
// Whh packed per gate-col: 8 iters x 4 q x 4 words:
//   [0]=bf16x2(hi_{k+1},hi_k) [1]=bf16x2(hi_{k+9},hi_{k+8})
//   [2]=bf16x2(lo_{k+1},lo_k) [3]=bf16x2(lo_{k+9},lo_{k+8}),  k = it*16+2q
__device__ unsigned g_Bh[GCOLS*HID];
__device__ unsigned g_Bf[GCOLS*HID];
__device__ float g_bih_h[GCOLS], g_bhh_h[GCOLS], g_W0_h[GCOLS], g_Wx_h[GCOLS];
__device__ float g_bih_f[GCOLS], g_bhh_f[GCOLS], g_W0_f[GCOLS], g_Wx_f[GCOLS*9];

__device__ __forceinline__ float sigf(float x)   { return 1.0f/(1.0f + __expf(-x)); }
__device__ __forceinline__ float tanhfast(float x){ return 2.0f/(1.0f + __expf(-2.0f*x)) - 1.0f; }

__device__ __forceinline__ unsigned bf16x2_of(float hi_val, float lo_val) {
    unsigned w; asm("cvt.rn.bf16x2.f32 %0, %1, %2;" : "=r"(w) : "f"(hi_val), "f"(lo_val));
    return w;   // high16 = hi_val, low16 = lo_val
}
__device__ __forceinline__ float bf16_round(float x) {
    unsigned h; asm("cvt.rn.bf16x2.f32 %0, %1, %1;" : "=r"(h) : "f"(x));
    return __uint_as_float(h << 16);
}
__device__ __forceinline__ float lo16f(unsigned w) { return __uint_as_float(w << 16); }
__device__ __forceinline__ float hi16f(unsigned w) { return __uint_as_float(w & 0xFFFF0000u); }

__device__ __forceinline__ void mma_s(float* d, unsigned a0, unsigned a1, unsigned a2, unsigned a3,
                                      unsigned b0, unsigned b1) {
    asm volatile("mma.sync.aligned.m16n8k16.row.col.f32.bf16.bf16.f32 "
        "{%0,%1,%2,%3}, {%4,%5,%6,%7}, {%8,%9}, {%0,%1,%2,%3};"
        : "+f"(d[0]), "+f"(d[1]), "+f"(d[2]), "+f"(d[3])
        : "r"(a0), "r"(a1), "r"(a2), "r"(a3), "r"(b0), "r"(b1));
}

// ---------------- prep ----------------
__global__ void prep_kernel(const float* __restrict__ angles,
                            const float* __restrict__ Whh_h, const float* __restrict__ Whh_f,
                            const float* __restrict__ Wih_h, const float* __restrict__ bih_h,
                            const float* __restrict__ bhh_h,
                            const float* __restrict__ Wih_f, const float* __restrict__ bih_f,
                            const float* __restrict__ bhh_f) {
    int i = blockIdx.x*blockDim.x + threadIdx.x;
    if (i < NNODE*NNODE) {
        float a = angles[i];
        g_comp1[i] = cosf(a);
        g_comp2[i] = cosf(a - 1.57079632679489662f);
    }
    if (i < GCOLS*32) {
        int gc = i >> 5, r5 = i & 31;
        int it = r5 >> 2, qq = r5 & 3;
        int k0 = it*16 + qq*2;
        unsigned* dsth = g_Bh + gc*128 + it*16 + qq*4;
        unsigned* dstf = g_Bf + gc*128 + it*16 + qq*4;
        const float* Wh = Whh_h + gc*128;
        const float* Wf = Whh_f + gc*128;
        {
            float w0 = Wh[k0], w1 = Wh[k0+1], w8 = Wh[k0+8], w9 = Wh[k0+9];
            dsth[0] = bf16x2_of(w1, w0);
            dsth[1] = bf16x2_of(w9, w8);
            dsth[2] = bf16x2_of(w1 - bf16_round(w1), w0 - bf16_round(w0));
            dsth[3] = bf16x2_of(w9 - bf16_round(w9), w8 - bf16_round(w8));
        }
        {
            float w0 = Wf[k0], w1 = Wf[k0+1], w8 = Wf[k0+8], w9 = Wf[k0+9];
            dstf[0] = bf16x2_of(w1, w0);
            dstf[1] = bf16x2_of(w9, w8);
            dstf[2] = bf16x2_of(w1 - bf16_round(w1), w0 - bf16_round(w0));
            dstf[3] = bf16x2_of(w9 - bf16_round(w9), w8 - bf16_round(w8));
        }
    }
    if (i < GCOLS) {
        g_bih_h[i] = bih_h[i]; g_bhh_h[i] = bhh_h[i];
        g_W0_h[i]  = Wih_h[i*2]; g_Wx_h[i] = Wih_h[i*2+1];
        g_bih_f[i] = bih_f[i]; g_bhh_f[i] = bhh_f[i];
        g_W0_f[i]  = Wih_f[i*10];
        for (int k = 0; k < 9; k++) g_Wx_f[i*9+k] = Wih_f[i*10+1+k];
    }
}

__global__ void zero_kernel() {
    int i = blockIdx.x*blockDim.x + threadIdx.x;
    if (i < M_ROWS*HID) g_hpA[i] = 0u;
}

// ---------------- fused step: G = h@Whh^T (3-MMA bf16 split) + GRU gates ----------------
// Grid (8 col-groups, 368 row-groups), 256 threads = 8 warps, ALL M-stacked.
// Block tile: 128 rows x 48 gate cols (16 hu x {r,z,n}); warp tile 16 rows x 48 cols.
#define SB_STRIDE 144
#define SMEM_FLOATS (48*SB_STRIDE + 128*9 + 48*9 + 48*3 + 128 + 16)
#define SMEM_BYTES  (SMEM_FLOATS*4)

template<int NF>
__global__ __launch_bounds__(256, 4) void fused_step(int par, int t, int xn_mode,
        const float* __restrict__ pm25,
        const float* __restrict__ fcw, const float* __restrict__ fcb) {
    extern __shared__ float sm[];
    unsigned* sB = (unsigned*)sm;        // [48][144] packed bf16x2 words
    float* sX   = sm  + 48*SB_STRIDE;    // [128][<=9] input feats
    float* sWx  = sX  + 128*9;           // [48][<=9]
    float* sW0  = sWx + 48*9;            // [48]
    float* sbih = sW0 + 48;
    float* sbhh = sbih + 48;
    float* sxn  = sbhh + 48;             // [128]
    float* sfcw = sxn + 128;             // [16]

    const unsigned* hin  = par ? g_hpB : g_hpA;
    unsigned*       hout = par ? g_hpA : g_hpB;
    const unsigned* Bw = (NF==1) ? g_Bh : g_Bf;
    const float* bih = (NF==1) ? g_bih_h : g_bih_f;
    const float* bhh = (NF==1) ? g_bhh_h : g_bhh_f;
    const float* Wx  = (NF==1) ? g_Wx_h  : g_Wx_f;
    const float* W0  = (NF==1) ? g_W0_h  : g_W0_f;

    const int tid  = threadIdx.x;
    const int cg   = blockIdx.x;              // hidden units [cg*16, cg*16+16)
    const int row0 = blockIdx.y * 128;

    // ---- stage B: 48 gate cols (3 gates x 16 local hu) ----
    for (int i = tid; i < 48*32; i += 256) {
        int c = i >> 5, f = (i & 31) << 2;
        int gcol = ((c >> 4) << 7) + (cg << 4) + (c & 15);
        *(uint4*)(sB + c*SB_STRIDE + f) = *(const uint4*)(Bw + gcol*128 + f);
    }
    if (tid < 48) {
        int gcol = ((tid >> 4) << 7) + (cg << 4) + (tid & 15);
        sbih[tid] = bih[gcol]; sbhh[tid] = bhh[gcol]; sW0[tid] = W0[gcol];
#pragma unroll
        for (int k = 0; k < NF; k++) sWx[tid*NF + k] = Wx[gcol*NF + k];
    }
    if (tid >= 48 && tid < 64) sfcw[tid-48] = fcw[(cg<<4) + (tid-48)];
    if (tid < 128) {
        int row = row0 + tid;
        if (NF == 1) {
            int b = row / NNODE, n = row - b*NNODE;
            sX[tid] = pm25[((size_t)b*TH + t)*NNODE + n];
        } else {
#pragma unroll
            for (int k = 0; k < 9; k++) sX[tid*9 + k] = g_x2[(size_t)row*9 + k];
        }
        if (xn_mode == 1) {
            float s = fcb[0];
#pragma unroll
            for (int c2 = 0; c2 < 8; c2++) s += g_xnpart[c2*M_ROWS + row];
            sxn[tid] = s;
        } else if (xn_mode == 2) {
            sxn[tid] = g_xn[row];
        }
    }
    __syncthreads();

    const int lane = tid & 31, w = tid >> 5;
    const int g = lane >> 2, q = lane & 3;
    const int rbase = (w << 4) + g;           // warp owns rows [w*16, w*16+16)

    float acc[24];                            // [jn6][4]
#pragma unroll
    for (int i = 0; i < 24; i++) acc[i] = 0.0f;

    const unsigned* h0 = hin + (size_t)(row0 + rbase)*HID;   // row g
    const unsigned* h1 = h0 + 8*HID;                          // row g+8
    const unsigned* pbw = sB + g*SB_STRIDE + 4*q;

#pragma unroll
    for (int it = 0; it < 8; it++) {
        const int ko = it*16 + 4*q;
        uint4 A0 = *(const uint4*)(h0 + ko);   // {hi01, hi89, lo01, lo89} row g
        uint4 A1 = *(const uint4*)(h1 + ko);   // row g+8
#pragma unroll
        for (int jp = 0; jp < 3; jp++) {       // jn pairs (2jp, 2jp+1)
            uint4 ba = *(const uint4*)(pbw + (2*jp  )*8*SB_STRIDE + it*16);
            uint4 bb = *(const uint4*)(pbw + (2*jp+1)*8*SB_STRIDE + it*16);
            float* da = acc + (2*jp)*4;
            float* db = acc + (2*jp+1)*4;
            mma_s(da, A0.x, A1.x, A0.y, A1.y, ba.x, ba.y);   // hi*hi  jn=2jp
            mma_s(db, A0.x, A1.x, A0.y, A1.y, bb.x, bb.y);   // hi*hi  jn=2jp+1
            mma_s(da, A0.z, A1.z, A0.w, A1.w, ba.x, ba.y);   // lo*hi
            mma_s(db, A0.z, A1.z, A0.w, A1.w, bb.x, bb.y);
            mma_s(da, A0.x, A1.x, A0.y, A1.y, ba.z, ba.w);   // hi*lo
            mma_s(db, A0.x, A1.x, A0.y, A1.y, bb.z, bb.w);
        }
    }

    // ---- epilogue: gates + h update + fc partials ----
    float part[2];
#pragma unroll
    for (int rh = 0; rh < 2; rh++) {
        int lrow = rbase + rh*8;               // local row
        size_t base = (size_t)(row0 + lrow)*HID + (cg<<4) + q*4;
        uint4 hw = *(const uint4*)(hin + base);
        float hold[4];
        hold[0] = lo16f(hw.x) + lo16f(hw.z);
        hold[1] = hi16f(hw.x) + hi16f(hw.z);
        hold[2] = lo16f(hw.y) + lo16f(hw.w);
        hold[3] = hi16f(hw.y) + hi16f(hw.w);
        float xnv = (xn_mode == 0) ? 0.0f : sxn[lrow];
        float hnew[4];
        float psum = 0.0f;
#pragma unroll
        for (int s = 0; s < 4; s++) {
            int jj = s >> 1, e = s & 1;
            int l16 = jj*8 + 2*q + e;          // block-local hu [0,16)
            float gir = sbih[l16]    + xnv*sW0[l16];
            float giz = sbih[16+l16] + xnv*sW0[16+l16];
            float gin = sbih[32+l16] + xnv*sW0[32+l16];
#pragma unroll
            for (int k = 0; k < NF; k++) {
                float xk = (NF == 1) ? sX[lrow] : sX[lrow*9 + k];
                gir = fmaf(xk, sWx[l16*NF + k],      gir);
                giz = fmaf(xk, sWx[(16+l16)*NF + k], giz);
                gin = fmaf(xk, sWx[(32+l16)*NF + k], gin);
            }
            int d = rh*2 + e;
            float rr = sigf(gir + acc[ jj   *4 + d] + sbhh[l16]);
            float zz = sigf(giz + acc[(2+jj)*4 + d] + sbhh[16+l16]);
            float nn = tanhfast(gin + rr*(acc[(4+jj)*4 + d] + sbhh[32+l16]));
            float hv = (1.0f - zz)*nn + zz*hold[s];
            hnew[s] = hv;
            psum += hv * sfcw[l16];
        }
        float hb0 = bf16_round(hnew[0]), hb1 = bf16_round(hnew[1]);
        float hb2 = bf16_round(hnew[2]), hb3 = bf16_round(hnew[3]);
        uint4 ow;
        ow.x = bf16x2_of(hnew[1], hnew[0]);                 // hi pair k01
        ow.y = bf16x2_of(hnew[3], hnew[2]);                 // hi pair k89
        ow.z = bf16x2_of(hnew[1] - hb1, hnew[0] - hb0);     // lo pair k01
        ow.w = bf16x2_of(hnew[3] - hb3, hnew[2] - hb2);     // lo pair k89
        *(uint4*)(hout + base) = ow;
        part[rh] = psum;
    }
    // reduce partials over q lanes and store (16-hu group = slot cg)
#pragma unroll
    for (int pi = 0; pi < 2; pi++) {
        float p = part[pi];
        p += __shfl_xor_sync(0xffffffffu, p, 1);
        p += __shfl_xor_sync(0xffffffffu, p, 2);
        if (q == 0) g_xnpart[cg*M_ROWS + row0 + rbase + pi*8] = p;
    }
}

// ---------------- graph: xn (from partials) + wind-gated ChebConv gate -> g_x2 ------
__global__ __launch_bounds__(256) void graph_kernel(int t,
        const float* __restrict__ feature, const float* __restrict__ adj,
        const float* __restrict__ cw0, const float* __restrict__ cw1,
        const float* __restrict__ cb, const float* __restrict__ fcb,
        float* __restrict__ out) {
    int b   = blockIdx.x;
    int tid = threadIdx.x;
    __shared__ float sx[NNODE][9];
    __shared__ float sdinv[NNODE];
    __shared__ float shneg[NNODE];
    __shared__ unsigned int sM[NNODE][6];

    const float* fb = feature + (((size_t)b*(TH+TF) + TH + t)*NNODE)*8;
    for (int i = tid; i < NNODE; i += 256) {
#pragma unroll
        for (int c = 0; c < 8; c++) sx[i][1+c] = fb[i*8 + c];
        int row = b*NNODE + i;
        float s = fcb[0];
#pragma unroll
        for (int c2 = 0; c2 < 8; c2++) s += g_xnpart[c2*M_ROWS + row];
        sx[i][0] = s;
        g_xn[row] = s;
        if (t > 0) out[((size_t)b*TF + (t-1))*NNODE + i] = s;
    }
    __syncthreads();

    // pass 1: per-source-node edge bitmask + degree
    for (int i = tid; i < NNODE; i += 256) {
        float u = sx[i][1];
        float v = sx[i][2];
        const float* c1 = g_comp1 + i*NNODE;
        const float* c2 = g_comp2 + i*NNODE;
        const float* ar = adj     + i*NNODE;
        int deg = 0;
        for (int qq = 0; qq < 6; qq++) {
            unsigned bits = 0;
            int jend = (qq == 5) ? (NNODE - 160) : 32;
            for (int jj = 0; jj < jend; jj++) {
                int j = qq*32 + jj;
                float w = u*c1[j] + v*c2[j];
                if (w >= 0.5f && ar[j] > 0.0f) { deg++; bits |= (1u << jj); }
            }
            sM[i][qq] = bits;
        }
        sdinv[i] = (deg > 0) ? (1.0f / sqrtf((float)deg)) : 0.0f;
        shneg[i] = (deg > 0) ? 0.0f : -1.0f;
    }
    __syncthreads();

    // pass 2: ChebConv y, gate g, write g_x2 = [f0..f7, g]
    for (int j = tid; j < NNODE; j += 256) {
        float y[9];
#pragma unroll
        for (int c = 0; c < 9; c++) y[c] = 0.0f;
        int qq = j >> 5, sh = j & 31;
        for (int i = 0; i < NNODE; i++) {
            float w = ((sM[i][qq] >> sh) & 1u) ? sdinv[i] : 0.0f;
#pragma unroll
            for (int c = 0; c < 9; c++) y[c] = fmaf(w, sx[i][c], y[c]);
        }
        float dj = sdinv[j], hn = shneg[j];
        float acc = cb[0];
#pragma unroll
        for (int c = 0; c < 9; c++) {
            float yc = fmaf(-dj, y[c], hn*sx[j][c]);
            acc += sx[j][c]*cw0[c] + yc*cw1[c];
        }
        float gte = sigf(acc);
        float* o = g_x2 + (size_t)(b*NNODE + j)*9;
#pragma unroll
        for (int c = 0; c < 8; c++) o[c] = sx[j][1+c];
        o[8] = gte;
    }
}

// ---------------- final prediction (t = TF-1) from last partials ----------------
__global__ __launch_bounds__(256) void pred_kernel(const float* __restrict__ fcb,
                                                   float* __restrict__ out) {
    int row = blockIdx.x*256 + threadIdx.x;
    float s = fcb[0];
#pragma unroll
    for (int c2 = 0; c2 < 8; c2++) s += g_xnpart[c2*M_ROWS + row];
    int b = row / NNODE, n = row - b*NNODE;
    out[((size_t)b*TF + (TF-1))*NNODE + n] = s;
}

// ---------------- launch ----------------
extern "C" void kernel_launch(void* const* d_in, const int* in_sizes, int n_in,
                              void* d_out, int out_size) {
    const float* feature   = (const float*)d_in[0];
    const float* pm25      = (const float*)d_in[1];
    const float* adj       = (const float*)d_in[2];
    const float* angles    = (const float*)d_in[3];
    const float* W_ih_hist = (const float*)d_in[4];
    const float* W_hh_hist = (const float*)d_in[5];
    const float* b_ih_hist = (const float*)d_in[6];
    const float* b_hh_hist = (const float*)d_in[7];
    const float* fc_hist_w = (const float*)d_in[8];
    const float* fc_hist_b = (const float*)d_in[9];
    const float* cheb_w0   = (const float*)d_in[10];
    const float* cheb_w1   = (const float*)d_in[11];
    const float* cheb_b    = (const float*)d_in[12];
    const float* W_ih      = (const float*)d_in[13];
    const float* W_hh      = (const float*)d_in[14];
    const float* b_ih      = (const float*)d_in[15];
    const float* b_hh      = (const float*)d_in[16];
    const float* fc_out_w  = (const float*)d_in[17];
    const float* fc_out_b  = (const float*)d_in[18];
    float* out = (float*)d_out;

    cudaFuncSetAttribute(fused_step<1>, cudaFuncAttributeMaxDynamicSharedMemorySize, SMEM_BYTES);
    cudaFuncSetAttribute(fused_step<9>, cudaFuncAttributeMaxDynamicSharedMemorySize, SMEM_BYTES);

    prep_kernel<<<(NNODE*NNODE + 255)/256, 256>>>(angles, W_hh_hist, W_hh,
                                                  W_ih_hist, b_ih_hist, b_hh_hist,
                                                  W_ih, b_ih, b_hh);
    zero_kernel<<<(M_ROWS*HID + 255)/256, 256>>>();

    dim3 fgrid(8, M_ROWS/128);   // (8, 368)

    for (int t = 0; t < TH; t++) {
        fused_step<1><<<fgrid, 256, SMEM_BYTES>>>(t & 1, t, (t == 0) ? 0 : 1,
                                                  pm25, fc_hist_w, fc_hist_b);
    }
    for (int t = 0; t < TF; t++) {
        int s = TH + t;
        graph_kernel<<<BATCH, 256>>>(t, feature, adj, cheb_w0, cheb_w1, cheb_b,
                                     (t == 0) ? fc_hist_b : fc_out_b, out);
        fused_step<9><<<fgrid, 256, SMEM_BYTES>>>(s & 1, t, 2,
                                                  pm25, fc_out_w, fc_out_b);
    }
    pred_kernel<<<M_ROWS/256, 256>>>(fc_out_b, out);
}

// round 15
// speedup vs baseline: 1.5993x; 1.5993x over previous
#include <cuda_runtime.h>
#include <math.h>

#define BATCH 256
#define NNODE 184
#define HID   128
#define TH    24
#define TF    24
#define M_ROWS (BATCH*NNODE)      /* 47104 = 368*128 */
#define GCOLS  (3*HID)            /* 384 */

// ---------------- persistent device scratch ----------------
// h stored FRAGMENT-DIRECT per row (128 words):
//   uint4 at word offset it*16 + q*4 = { bf16x2(hi_{k+1},hi_k), bf16x2(hi_{k+9},hi_{k+8}),
//                                        bf16x2(lo_{k+1},lo_k), bf16x2(lo_{k+9},lo_{k+8}) }
__device__ unsigned g_hpA[(size_t)M_ROWS*HID];
__device__ unsigned g_hpB[(size_t)M_ROWS*HID];
__device__ float g_xn[M_ROWS];
__device__ float g_xnpart[8*M_ROWS];             // per-16hu-group fc partial sums
__device__ float g_x2[(size_t)M_ROWS*9];         // fore GRU input feats [f0..f7, g]
__device__ float g_comp1[NNODE*NNODE];
__device__ float g_comp2[NNODE*NNODE];
// Whh packed per gate-col (fragment layout, 128 words)
__device__ unsigned g_Bh[GCOLS*HID];
__device__ unsigned g_Bf[GCOLS*HID];
// Wih (+fused biases) packed per gate-col (fragment layout, 16 words = one K16 slice)
//   x vector: hist = [xn, pm25, 1, 0...], fore = [xn, f0..f7, g, 1, 0...]
//   bias slot weight: r/z gates -> bih+bhh (fully summable), n gate -> bih only
__device__ unsigned g_BxH[GCOLS*16];
__device__ unsigned g_BxF[GCOLS*16];
__device__ float g_bhh_h[GCOLS], g_bhh_f[GCOLS];

__device__ __forceinline__ float sigf(float x)   { return 1.0f/(1.0f + __expf(-x)); }
__device__ __forceinline__ float tanhfast(float x){ return 2.0f/(1.0f + __expf(-2.0f*x)) - 1.0f; }

__device__ __forceinline__ unsigned bf16x2_of(float hi_val, float lo_val) {
    unsigned w; asm("cvt.rn.bf16x2.f32 %0, %1, %2;" : "=r"(w) : "f"(hi_val), "f"(lo_val));
    return w;   // high16 = hi_val, low16 = lo_val
}
__device__ __forceinline__ float bf16_round(float x) {
    unsigned h; asm("cvt.rn.bf16x2.f32 %0, %1, %1;" : "=r"(h) : "f"(x));
    return __uint_as_float(h << 16);
}
__device__ __forceinline__ float lo16f(unsigned w) { return __uint_as_float(w << 16); }
__device__ __forceinline__ float hi16f(unsigned w) { return __uint_as_float(w & 0xFFFF0000u); }

__device__ __forceinline__ void mma_s(float* d, unsigned a0, unsigned a1, unsigned a2, unsigned a3,
                                      unsigned b0, unsigned b1) {
    asm volatile("mma.sync.aligned.m16n8k16.row.col.f32.bf16.bf16.f32 "
        "{%0,%1,%2,%3}, {%4,%5,%6,%7}, {%8,%9}, {%0,%1,%2,%3};"
        : "+f"(d[0]), "+f"(d[1]), "+f"(d[2]), "+f"(d[3])
        : "r"(a0), "r"(a1), "r"(a2), "r"(a3), "r"(b0), "r"(b1));
}

// pack 16 fp32 values into the 16-word fragment-direct hi/lo layout
__device__ __forceinline__ void pack16(const float* xv, unsigned* dst) {
#pragma unroll
    for (int qq = 0; qq < 4; qq++) {
        float a0 = xv[2*qq], a1 = xv[2*qq+1], b0 = xv[2*qq+8], b1 = xv[2*qq+9];
        dst[qq*4+0] = bf16x2_of(a1, a0);
        dst[qq*4+1] = bf16x2_of(b1, b0);
        dst[qq*4+2] = bf16x2_of(a1 - bf16_round(a1), a0 - bf16_round(a0));
        dst[qq*4+3] = bf16x2_of(b1 - bf16_round(b1), b0 - bf16_round(b0));
    }
}

// ---------------- prep ----------------
__global__ void prep_kernel(const float* __restrict__ angles,
                            const float* __restrict__ Whh_h, const float* __restrict__ Whh_f,
                            const float* __restrict__ Wih_h, const float* __restrict__ bih_h,
                            const float* __restrict__ bhh_h,
                            const float* __restrict__ Wih_f, const float* __restrict__ bih_f,
                            const float* __restrict__ bhh_f) {
    int i = blockIdx.x*blockDim.x + threadIdx.x;
    if (i < NNODE*NNODE) {
        float a = angles[i];
        g_comp1[i] = cosf(a);
        g_comp2[i] = cosf(a - 1.57079632679489662f);
    }
    if (i < GCOLS*32) {     // Whh fragment packing (4 words per thread-slot)
        int gc = i >> 5, r5 = i & 31;
        int it = r5 >> 2, qq = r5 & 3;
        int k0 = it*16 + qq*2;
        unsigned* dsth = g_Bh + gc*128 + it*16 + qq*4;
        unsigned* dstf = g_Bf + gc*128 + it*16 + qq*4;
        const float* Wh = Whh_h + gc*128;
        const float* Wf = Whh_f + gc*128;
        {
            float w0 = Wh[k0], w1 = Wh[k0+1], w8 = Wh[k0+8], w9 = Wh[k0+9];
            dsth[0] = bf16x2_of(w1, w0);
            dsth[1] = bf16x2_of(w9, w8);
            dsth[2] = bf16x2_of(w1 - bf16_round(w1), w0 - bf16_round(w0));
            dsth[3] = bf16x2_of(w9 - bf16_round(w9), w8 - bf16_round(w8));
        }
        {
            float w0 = Wf[k0], w1 = Wf[k0+1], w8 = Wf[k0+8], w9 = Wf[k0+9];
            dstf[0] = bf16x2_of(w1, w0);
            dstf[1] = bf16x2_of(w9, w8);
            dstf[2] = bf16x2_of(w1 - bf16_round(w1), w0 - bf16_round(w0));
            dstf[3] = bf16x2_of(w9 - bf16_round(w9), w8 - bf16_round(w8));
        }
    }
    if (i < GCOLS) {        // Wih (+bias) fragment packing, one gate-col per thread
        int gc = i;
        int gate = gc >> 7;             // 0=r 1=z 2=n
        float xw[16];
#pragma unroll
        for (int k = 0; k < 16; k++) xw[k] = 0.0f;
        xw[0] = Wih_h[gc*2];  xw[1] = Wih_h[gc*2+1];
        xw[2] = (gate < 2) ? (bih_h[gc] + bhh_h[gc]) : bih_h[gc];
        pack16(xw, g_BxH + gc*16);
#pragma unroll
        for (int k = 0; k < 16; k++) xw[k] = 0.0f;
#pragma unroll
        for (int k = 0; k < 10; k++) xw[k] = Wih_f[gc*10 + k];
        xw[10] = (gate < 2) ? (bih_f[gc] + bhh_f[gc]) : bih_f[gc];
        pack16(xw, g_BxF + gc*16);
        g_bhh_h[gc] = bhh_h[gc];
        g_bhh_f[gc] = bhh_f[gc];
    }
}

__global__ void zero_kernel() {
    int i = blockIdx.x*blockDim.x + threadIdx.x;
    if (i < M_ROWS*HID) g_hpA[i] = 0u;
}

// ---------------- fused step: [gh | gi] via bf16-split MMA + GRU gates ----------------
// Grid (8 col-groups, 368 row-groups), 256 threads = 8 warps, M-stacked.
// Block tile: 128 rows x 48 gate cols (16 hu x {r,z,n}); warp tile 16 rows x 48 cols.
#define SB_STRIDE 144
#define SMEM_WORDS (48*SB_STRIDE + 48*16 + 128*16 + 16 + 16)
#define SMEM_BYTES (SMEM_WORDS*4)

template<int NF>
__global__ __launch_bounds__(256, 4) void fused_step(int par, int t, int xn_mode,
        const float* __restrict__ pm25,
        const float* __restrict__ fcw, const float* __restrict__ fcb) {
    extern __shared__ float sm[];
    unsigned* sB   = (unsigned*)sm;          // [48][144] Whh packed words
    unsigned* sBx  = sB  + 48*SB_STRIDE;     // [48][16]  Wih(+bias) packed words
    unsigned* sXp  = sBx + 48*16;            // [128][16] packed x fragments
    float*    sbhn = (float*)(sXp + 128*16); // [16] bhh (n gate)
    float*    sfcw = sbhn + 16;              // [16]

    const unsigned* hin  = par ? g_hpB : g_hpA;
    unsigned*       hout = par ? g_hpA : g_hpB;
    const unsigned* Bw  = (NF==1) ? g_Bh  : g_Bf;
    const unsigned* Bx  = (NF==1) ? g_BxH : g_BxF;
    const float*    bhh = (NF==1) ? g_bhh_h : g_bhh_f;

    const int tid  = threadIdx.x;
    const int cg   = blockIdx.x;              // hidden units [cg*16, cg*16+16)
    const int row0 = blockIdx.y * 128;

    // ---- stage B (Whh): 48 gate cols ----
    for (int i = tid; i < 48*32; i += 256) {
        int c = i >> 5, f = (i & 31) << 2;
        int gcol = ((c >> 4) << 7) + (cg << 4) + (c & 15);
        *(uint4*)(sB + c*SB_STRIDE + f) = *(const uint4*)(Bw + gcol*128 + f);
    }
    // ---- stage Bx (Wih+bias) ----
    for (int i = tid; i < 48*16; i += 256) {
        int c = i >> 4, wsl = i & 15;
        int gcol = ((c >> 4) << 7) + (cg << 4) + (c & 15);
        sBx[c*16 + wsl] = Bx[gcol*16 + wsl];
    }
    if (tid < 16) sbhn[tid] = bhh[2*HID + (cg<<4) + tid];
    else if (tid < 32) sfcw[tid-16] = fcw[(cg<<4) + (tid-16)];
    // ---- stage packed x fragments ----
    if (tid < 128) {
        int row = row0 + tid;
        float xv[16];
#pragma unroll
        for (int k = 0; k < 16; k++) xv[k] = 0.0f;
        if (NF == 1) {
            float xn = 0.0f;
            if (xn_mode == 1) {
                xn = fcb[0];
#pragma unroll
                for (int c2 = 0; c2 < 8; c2++) xn += g_xnpart[c2*M_ROWS + row];
            }
            int b = row / NNODE, n = row - b*NNODE;
            xv[0] = xn;
            xv[1] = pm25[((size_t)b*TH + t)*NNODE + n];
            xv[2] = 1.0f;
        } else {
            xv[0] = g_xn[row];
#pragma unroll
            for (int k = 0; k < 9; k++) xv[1+k] = g_x2[(size_t)row*9 + k];
            xv[10] = 1.0f;
        }
        pack16(xv, sXp + tid*16);
    }
    __syncthreads();

    const int lane = tid & 31, w = tid >> 5;
    const int g = lane >> 2, q = lane & 3;
    const int rbase = (w << 4) + g;           // warp owns rows [w*16, w*16+16)

    float acc[24];                            // [jn6][4] : jn0,1=r  jn2,3=z  jn4,5=ghn
    float accN[8];                            // gin (+bin) for the two n-gate jn
#pragma unroll
    for (int i = 0; i < 24; i++) acc[i] = 0.0f;
#pragma unroll
    for (int i = 0; i < 8; i++) accN[i] = 0.0f;

    const unsigned* h0 = hin + (size_t)(row0 + rbase)*HID;   // row g
    const unsigned* h1 = h0 + 8*HID;                          // row g+8
    const unsigned* pbw = sB + g*SB_STRIDE + 4*q;

#pragma unroll
    for (int it = 0; it < 8; it++) {
        const int ko = it*16 + 4*q;
        uint4 A0 = *(const uint4*)(h0 + ko);   // {hi01, hi89, lo01, lo89} row g
        uint4 A1 = *(const uint4*)(h1 + ko);   // row g+8
#pragma unroll
        for (int jp = 0; jp < 3; jp++) {       // jn pairs (2jp, 2jp+1)
            uint4 ba = *(const uint4*)(pbw + (2*jp  )*8*SB_STRIDE + it*16);
            uint4 bb = *(const uint4*)(pbw + (2*jp+1)*8*SB_STRIDE + it*16);
            float* da = acc + (2*jp)*4;
            float* db = acc + (2*jp+1)*4;
            mma_s(da, A0.x, A1.x, A0.y, A1.y, ba.x, ba.y);   // hi*hi
            mma_s(db, A0.x, A1.x, A0.y, A1.y, bb.x, bb.y);
            mma_s(da, A0.z, A1.z, A0.w, A1.w, ba.x, ba.y);   // lo*hi
            mma_s(db, A0.z, A1.z, A0.w, A1.w, bb.x, bb.y);
            mma_s(da, A0.x, A1.x, A0.y, A1.y, ba.z, ba.w);   // hi*lo
            mma_s(db, A0.x, A1.x, A0.y, A1.y, bb.z, bb.w);
        }
    }
    // ---- x iteration: gi = x @ Wih^T (+biases). r/z -> acc, n -> accN ----
    {
        uint4 X0 = *(const uint4*)(sXp + rbase*16 + 4*q);
        uint4 X1 = *(const uint4*)(sXp + (rbase+8)*16 + 4*q);
        const unsigned* pbx = sBx + g*16 + 4*q;
#pragma unroll
        for (int jp = 0; jp < 3; jp++) {
            uint4 ba = *(const uint4*)(pbx + (2*jp  )*8*16);
            uint4 bb = *(const uint4*)(pbx + (2*jp+1)*8*16);
            float* da = (jp < 2) ? (acc + (2*jp)*4)   : (accN + 0);
            float* db = (jp < 2) ? (acc + (2*jp+1)*4) : (accN + 4);
            mma_s(da, X0.x, X1.x, X0.y, X1.y, ba.x, ba.y);
            mma_s(db, X0.x, X1.x, X0.y, X1.y, bb.x, bb.y);
            mma_s(da, X0.z, X1.z, X0.w, X1.w, ba.x, ba.y);
            mma_s(db, X0.z, X1.z, X0.w, X1.w, bb.x, bb.y);
            mma_s(da, X0.x, X1.x, X0.y, X1.y, ba.z, ba.w);
            mma_s(db, X0.x, X1.x, X0.y, X1.y, bb.z, bb.w);
        }
    }

    // ---- epilogue: gates + h update + fc partials ----
    float part[2];
#pragma unroll
    for (int rh = 0; rh < 2; rh++) {
        int lrow = rbase + rh*8;
        size_t base = (size_t)(row0 + lrow)*HID + (cg<<4) + q*4;
        uint4 hw = *(const uint4*)(hin + base);
        float hold[4];
        hold[0] = lo16f(hw.x) + lo16f(hw.z);
        hold[1] = hi16f(hw.x) + hi16f(hw.z);
        hold[2] = lo16f(hw.y) + lo16f(hw.w);
        hold[3] = hi16f(hw.y) + hi16f(hw.w);
        float hnew[4];
        float psum = 0.0f;
#pragma unroll
        for (int s = 0; s < 4; s++) {
            int jj = s >> 1, e = s & 1;
            int l16 = jj*8 + 2*q + e;          // block-local hu [0,16)
            int d = rh*2 + e;
            float rr = sigf(acc[ jj   *4 + d]);
            float zz = sigf(acc[(2+jj)*4 + d]);
            float nn = tanhfast(accN[jj*4 + d] + rr*(acc[(4+jj)*4 + d] + sbhn[l16]));
            float hv = (1.0f - zz)*nn + zz*hold[s];
            hnew[s] = hv;
            psum += hv * sfcw[l16];
        }
        float hb0 = bf16_round(hnew[0]), hb1 = bf16_round(hnew[1]);
        float hb2 = bf16_round(hnew[2]), hb3 = bf16_round(hnew[3]);
        uint4 ow;
        ow.x = bf16x2_of(hnew[1], hnew[0]);
        ow.y = bf16x2_of(hnew[3], hnew[2]);
        ow.z = bf16x2_of(hnew[1] - hb1, hnew[0] - hb0);
        ow.w = bf16x2_of(hnew[3] - hb3, hnew[2] - hb2);
        *(uint4*)(hout + base) = ow;
        part[rh] = psum;
    }
#pragma unroll
    for (int pi = 0; pi < 2; pi++) {
        float p = part[pi];
        p += __shfl_xor_sync(0xffffffffu, p, 1);
        p += __shfl_xor_sync(0xffffffffu, p, 2);
        if (q == 0) g_xnpart[cg*M_ROWS + row0 + rbase + pi*8] = p;
    }
}

// ---------------- graph: xn (from partials) + wind-gated ChebConv gate -> g_x2 ------
__global__ __launch_bounds__(256) void graph_kernel(int t,
        const float* __restrict__ feature, const float* __restrict__ adj,
        const float* __restrict__ cw0, const float* __restrict__ cw1,
        const float* __restrict__ cb, const float* __restrict__ fcb,
        float* __restrict__ out) {
    int b   = blockIdx.x;
    int tid = threadIdx.x;
    __shared__ float sx[NNODE][9];
    __shared__ float sdinv[NNODE];
    __shared__ float shneg[NNODE];
    __shared__ unsigned int sM[NNODE][6];

    const float* fb = feature + (((size_t)b*(TH+TF) + TH + t)*NNODE)*8;
    for (int i = tid; i < NNODE; i += 256) {
#pragma unroll
        for (int c = 0; c < 8; c++) sx[i][1+c] = fb[i*8 + c];
        int row = b*NNODE + i;
        float s = fcb[0];
#pragma unroll
        for (int c2 = 0; c2 < 8; c2++) s += g_xnpart[c2*M_ROWS + row];
        sx[i][0] = s;
        g_xn[row] = s;
        if (t > 0) out[((size_t)b*TF + (t-1))*NNODE + i] = s;
    }
    __syncthreads();

    for (int i = tid; i < NNODE; i += 256) {
        float u = sx[i][1];
        float v = sx[i][2];
        const float* c1 = g_comp1 + i*NNODE;
        const float* c2 = g_comp2 + i*NNODE;
        const float* ar = adj     + i*NNODE;
        int deg = 0;
        for (int qq = 0; qq < 6; qq++) {
            unsigned bits = 0;
            int jend = (qq == 5) ? (NNODE - 160) : 32;
            for (int jj = 0; jj < jend; jj++) {
                int j = qq*32 + jj;
                float w = u*c1[j] + v*c2[j];
                if (w >= 0.5f && ar[j] > 0.0f) { deg++; bits |= (1u << jj); }
            }
            sM[i][qq] = bits;
        }
        sdinv[i] = (deg > 0) ? (1.0f / sqrtf((float)deg)) : 0.0f;
        shneg[i] = (deg > 0) ? 0.0f : -1.0f;
    }
    __syncthreads();

    for (int j = tid; j < NNODE; j += 256) {
        float y[9];
#pragma unroll
        for (int c = 0; c < 9; c++) y[c] = 0.0f;
        int qq = j >> 5, sh = j & 31;
        for (int i = 0; i < NNODE; i++) {
            float w = ((sM[i][qq] >> sh) & 1u) ? sdinv[i] : 0.0f;
#pragma unroll
            for (int c = 0; c < 9; c++) y[c] = fmaf(w, sx[i][c], y[c]);
        }
        float dj = sdinv[j], hn = shneg[j];
        float acc = cb[0];
#pragma unroll
        for (int c = 0; c < 9; c++) {
            float yc = fmaf(-dj, y[c], hn*sx[j][c]);
            acc += sx[j][c]*cw0[c] + yc*cw1[c];
        }
        float gte = sigf(acc);
        float* o = g_x2 + (size_t)(b*NNODE + j)*9;
#pragma unroll
        for (int c = 0; c < 8; c++) o[c] = sx[j][1+c];
        o[8] = gte;
    }
}

// ---------------- final prediction (t = TF-1) from last partials ----------------
__global__ __launch_bounds__(256) void pred_kernel(const float* __restrict__ fcb,
                                                   float* __restrict__ out) {
    int row = blockIdx.x*256 + threadIdx.x;
    float s = fcb[0];
#pragma unroll
    for (int c2 = 0; c2 < 8; c2++) s += g_xnpart[c2*M_ROWS + row];
    int b = row / NNODE, n = row - b*NNODE;
    out[((size_t)b*TF + (TF-1))*NNODE + n] = s;
}

// ---------------- launch ----------------
extern "C" void kernel_launch(void* const* d_in, const int* in_sizes, int n_in,
                              void* d_out, int out_size) {
    const float* feature   = (const float*)d_in[0];
    const float* pm25      = (const float*)d_in[1];
    const float* adj       = (const float*)d_in[2];
    const float* angles    = (const float*)d_in[3];
    const float* W_ih_hist = (const float*)d_in[4];
    const float* W_hh_hist = (const float*)d_in[5];
    const float* b_ih_hist = (const float*)d_in[6];
    const float* b_hh_hist = (const float*)d_in[7];
    const float* fc_hist_w = (const float*)d_in[8];
    const float* fc_hist_b = (const float*)d_in[9];
    const float* cheb_w0   = (const float*)d_in[10];
    const float* cheb_w1   = (const float*)d_in[11];
    const float* cheb_b    = (const float*)d_in[12];
    const float* W_ih      = (const float*)d_in[13];
    const float* W_hh      = (const float*)d_in[14];
    const float* b_ih      = (const float*)d_in[15];
    const float* b_hh      = (const float*)d_in[16];
    const float* fc_out_w  = (const float*)d_in[17];
    const float* fc_out_b  = (const float*)d_in[18];
    float* out = (float*)d_out;

    cudaFuncSetAttribute(fused_step<1>, cudaFuncAttributeMaxDynamicSharedMemorySize, SMEM_BYTES);
    cudaFuncSetAttribute(fused_step<9>, cudaFuncAttributeMaxDynamicSharedMemorySize, SMEM_BYTES);

    prep_kernel<<<(NNODE*NNODE + 255)/256, 256>>>(angles, W_hh_hist, W_hh,
                                                  W_ih_hist, b_ih_hist, b_hh_hist,
                                                  W_ih, b_ih, b_hh);
    zero_kernel<<<(M_ROWS*HID + 255)/256, 256>>>();

    dim3 fgrid(8, M_ROWS/128);   // (8, 368)

    for (int t = 0; t < TH; t++) {
        fused_step<1><<<fgrid, 256, SMEM_BYTES>>>(t & 1, t, (t == 0) ? 0 : 1,
                                                  pm25, fc_hist_w, fc_hist_b);
    }
    for (int t = 0; t < TF; t++) {
        int s = TH + t;
        graph_kernel<<<BATCH, 256>>>(t, feature, adj, cheb_w0, cheb_w1, cheb_b,
                                     (t == 0) ? fc_hist_b : fc_out_b, out);
        fused_step<9><<<fgrid, 256, SMEM_BYTES>>>(s & 1, t, 2,
                                                  pm25, fc_out_w, fc_out_b);
    }
    pred_kernel<<<M_ROWS/256, 256>>>(fc_out_b, out);
}